// round 4
// baseline (speedup 1.0000x reference)
#include <cuda_runtime.h>
#include <cstdint>

#define VTH 0.5f
#define TAU 0.2f

__device__ __forceinline__ float4 lif4(float4 v) {
    float u = v.x;
    float s0 = (u > VTH) ? 1.0f : 0.0f;
    u = TAU * u * (1.0f - s0) + v.y;
    float s1 = (u > VTH) ? 1.0f : 0.0f;
    u = TAU * u * (1.0f - s1) + v.z;
    float s2 = (u > VTH) ? 1.0f : 0.0f;
    u = TAU * u * (1.0f - s2) + v.w;
    float s3 = (u > VTH) ? 1.0f : 0.0f;
    return make_float4(s0, s1, s2, s3);
}

// 256-bit (8 x b32) global load/store with streaming (.cs) policy — sm_100+/sm_103a.
__device__ __forceinline__ void ld256_cs(const float* p, float4& a, float4& b) {
    asm volatile("ld.global.cs.v8.b32 {%0,%1,%2,%3,%4,%5,%6,%7}, [%8];"
                 : "=f"(a.x), "=f"(a.y), "=f"(a.z), "=f"(a.w),
                   "=f"(b.x), "=f"(b.y), "=f"(b.z), "=f"(b.w)
                 : "l"(p));
}
__device__ __forceinline__ void st256_cs(float* p, float4 a, float4 b) {
    asm volatile("st.global.cs.v8.b32 [%0], {%1,%2,%3,%4,%5,%6,%7,%8};"
                 :: "l"(p),
                    "f"(a.x), "f"(a.y), "f"(a.z), "f"(a.w),
                    "f"(b.x), "f"(b.y), "f"(b.z), "f"(b.w)
                 : "memory");
}

// Each 32B unit = 2 neurons (8 floats). Each thread: 2 units, loads front-batched.
__global__ void __launch_bounds__(256) lif_kernel_v8(const float* __restrict__ x,
                                                     float* __restrict__ out,
                                                     int n8) {
    int i0 = blockIdx.x * (blockDim.x * 2) + threadIdx.x;
    int i1 = i0 + blockDim.x;

    if (i1 < n8) {
        float4 a0, b0, a1, b1;
        ld256_cs(x + (size_t)i0 * 8, a0, b0);
        ld256_cs(x + (size_t)i1 * 8, a1, b1);
        float4 ra0 = lif4(a0), rb0 = lif4(b0);
        float4 ra1 = lif4(a1), rb1 = lif4(b1);
        st256_cs(out + (size_t)i0 * 8, ra0, rb0);
        st256_cs(out + (size_t)i1 * 8, ra1, rb1);
    } else if (i0 < n8) {
        float4 a0, b0;
        ld256_cs(x + (size_t)i0 * 8, a0, b0);
        st256_cs(out + (size_t)i0 * 8, lif4(a0), lif4(b0));
    }
}

// Tail: handles neurons [start, n4) with plain float4 accesses.
__global__ void lif_tail(const float4* __restrict__ x, float4* __restrict__ out,
                         int start, int n4) {
    int i = start + blockIdx.x * blockDim.x + threadIdx.x;
    if (i < n4) out[i] = lif4(__ldcs(&x[i]));
}

extern "C" void kernel_launch(void* const* d_in, const int* in_sizes, int n_in,
                              void* d_out, int out_size) {
    const float* x = (const float*)d_in[0];
    float* out = (float*)d_out;
    int n4 = out_size / 4;   // neurons (4 contiguous steps each)
    int n8 = n4 / 2;         // 32-byte units (2 neurons each)

    int threads = 256;
    int per_block = threads * 2;
    int blocks = (n8 + per_block - 1) / per_block;
    if (blocks > 0)
        lif_kernel_v8<<<blocks, threads>>>(x, out, n8);

    int done = n8 * 2;
    int rem = n4 - done;
    if (rem > 0)
        lif_tail<<<1, 32>>>((const float4*)x, (float4*)out, done, n4);
}

// round 5
// speedup vs baseline: 1.0486x; 1.0486x over previous
#include <cuda_runtime.h>

#define VTH 0.5f
#define TAU 0.2f

__device__ __forceinline__ float4 lif4(float4 v) {
    float u = v.x;
    float s0 = (u > VTH) ? 1.0f : 0.0f;
    u = TAU * u * (1.0f - s0) + v.y;
    float s1 = (u > VTH) ? 1.0f : 0.0f;
    u = TAU * u * (1.0f - s1) + v.z;
    float s2 = (u > VTH) ? 1.0f : 0.0f;
    u = TAU * u * (1.0f - s2) + v.w;
    float s3 = (u > VTH) ? 1.0f : 0.0f;
    return make_float4(s0, s1, s2, s3);
}

// x: [N, 4] f32, steps innermost. Each thread: 4 float4 neurons, all 4 loads
// front-batched (MLP_p1=4), streaming cache policy on loads and stores.
__global__ void __launch_bounds__(256) lif_kernel4(const float4* __restrict__ x,
                                                   float4* __restrict__ out,
                                                   int n4) {
    int base = blockIdx.x * (blockDim.x * 4) + threadIdx.x;
    int i0 = base;
    int i1 = base + blockDim.x;
    int i2 = base + 2 * blockDim.x;
    int i3 = base + 3 * blockDim.x;

    if (i3 < n4) {
        // Fast path (uniform within block): 4 independent loads back-to-back.
        float4 v0 = __ldcs(&x[i0]);
        float4 v1 = __ldcs(&x[i1]);
        float4 v2 = __ldcs(&x[i2]);
        float4 v3 = __ldcs(&x[i3]);
        float4 r0 = lif4(v0);
        float4 r1 = lif4(v1);
        float4 r2 = lif4(v2);
        float4 r3 = lif4(v3);
        __stcs(&out[i0], r0);
        __stcs(&out[i1], r1);
        __stcs(&out[i2], r2);
        __stcs(&out[i3], r3);
    } else {
        if (i0 < n4) __stcs(&out[i0], lif4(__ldcs(&x[i0])));
        if (i1 < n4) __stcs(&out[i1], lif4(__ldcs(&x[i1])));
        if (i2 < n4) __stcs(&out[i2], lif4(__ldcs(&x[i2])));
    }
}

extern "C" void kernel_launch(void* const* d_in, const int* in_sizes, int n_in,
                              void* d_out, int out_size) {
    const float4* x = (const float4*)d_in[0];
    float4* out = (float4*)d_out;
    int n4 = out_size / 4;  // neurons (4 contiguous f32 steps each)

    int threads = 256;
    int per_block = threads * 4;
    int blocks = (n4 + per_block - 1) / per_block;
    lif_kernel4<<<blocks, threads>>>(x, out, n4);
}